// round 2
// baseline (speedup 1.0000x reference)
#include <cuda_runtime.h>

// Problem dims
#define BB 16
#define MM 128
#define NHD 256
#define EHD 128
#define HD (2*NHD+EHD)   // 640
#define ROWS (BB*MM)     // 2048

// Scratch (static __device__, no allocations)
__device__ __align__(16) float d_aggE[ROWS*EHD];   // [2048][128]
__device__ __align__(16) float d_sA[ROWS];         // colsum of A
__device__ __align__(16) float d_AX[ROWS*NHD];     // A^T @ X  [2048][256]
__device__ __align__(16) float d_H[ROWS*HD];       // relu(concat) [2048][640]

// ---------------------------------------------------------------------------
// Kernel 1: aggE[b,j,:] = sum_i A[b,i,j] * E[b,i,j,:]  ;  sA[b,j] = sum_i A[b,i,j]
// grid (M/4, B), block 128.  Each warp owns one j; lane -> float4 over e.
// ---------------------------------------------------------------------------
__global__ void ereduce_kernel(const float* __restrict__ E,
                               const float* __restrict__ A) {
    __shared__ float As[4][MM];
    const int b   = blockIdx.y;
    const int j0  = blockIdx.x * 4;
    const int tid = threadIdx.x;
    const int jl  = tid >> 5;
    const int lane = tid & 31;

    // Load 4 columns of A[b,:,j0..j0+3] into smem
    const float* Ab = A + (long)b * MM * MM;
    for (int idx = tid; idx < 4 * MM; idx += 128) {
        int jj = idx & 3;
        int i  = idx >> 2;
        As[jj][i] = Ab[i * MM + j0 + jj];
    }
    __syncthreads();

    if (tid < 4) {
        float s = 0.f;
        #pragma unroll
        for (int i = 0; i < MM; i++) s += As[tid][i];
        d_sA[b * MM + j0 + tid] = s;
    }

    const int j = j0 + jl;
    const float4* Ep = (const float4*)E + ((long)(b * MM) * MM + j) * (EHD / 4) + lane;
    const long istride = (long)MM * (EHD / 4);   // 4096 float4 per i

    float4 acc = make_float4(0.f, 0.f, 0.f, 0.f);
    #pragma unroll 8
    for (int i = 0; i < MM; i++) {
        float a  = As[jl][i];
        float4 v = Ep[(long)i * istride];
        acc.x = fmaf(a, v.x, acc.x);
        acc.y = fmaf(a, v.y, acc.y);
        acc.z = fmaf(a, v.z, acc.z);
        acc.w = fmaf(a, v.w, acc.w);
    }
    ((float4*)d_aggE)[(b * MM + j) * (EHD / 4) + lane] = acc;
}

// ---------------------------------------------------------------------------
// Kernel 2: H[:, NHD+EHD : HD] = relu(X)   (X occupies the THIRD concat slot)
// ---------------------------------------------------------------------------
__global__ void relux_kernel(const float* __restrict__ X) {
    int idx = blockIdx.x * blockDim.x + threadIdx.x;  // float4 index, 131072 total
    int r   = idx >> 6;          // / (256/4)
    int c4  = idx & 63;
    float4 v = ((const float4*)X)[idx];
    v.x = fmaxf(v.x, 0.f);
    v.y = fmaxf(v.y, 0.f);
    v.z = fmaxf(v.z, 0.f);
    v.w = fmaxf(v.w, 0.f);
    *(float4*)&d_H[(long)r * HD + (NHD + EHD) + c4 * 4] = v;
}

// ---------------------------------------------------------------------------
// Generic fp32 tiled GEMM: C = Aop @ B
//   Aop[m,k] = A[m*lda + k]            (TRANSA = false)
//   Aop[m,k] = A[k*lda + m]            (TRANSA = true)
// Tiles: BM=BN=64, BK=16, 256 threads, 4x4 per-thread micro tile.
// M, N multiples of 64; K multiple of 16 (holds for all calls here).
// MODE 0: C = relu(acc + srow[r]*bias[n])      (H write)
// MODE 1: C = (acc + bias[n]) * wmul[r]        (final output)
// MODE 2: C = acc                              (raw, batched AX)
// ---------------------------------------------------------------------------
template<bool TRANSA, int MODE>
__global__ void gemm_kernel(const float* __restrict__ Ag, int lda, long strideA,
                            const float* __restrict__ Bg, int ldb, long strideB,
                            float* __restrict__ Cg, int ldc, long strideC,
                            int K,
                            const float* __restrict__ bias,
                            const float* __restrict__ srow,
                            const float* __restrict__ wmul) {
    __shared__ float As[16][68];
    __shared__ float Bs[16][68];

    const float* Ab = Ag + (long)blockIdx.z * strideA;
    const float* Bb = Bg + (long)blockIdx.z * strideB;
    float*       Cb = Cg + (long)blockIdx.z * strideC;

    const int m0 = blockIdx.x * 64;
    const int n0 = blockIdx.y * 64;
    const int tid = threadIdx.x;
    const int tx = tid & 15;    // n: tx*4
    const int ty = tid >> 4;    // m: ty*4

    float acc[4][4] = {};

    for (int k0 = 0; k0 < K; k0 += 16) {
        // --- load A tile into As[k][m] ---
        if (TRANSA) {
            // A stored [k][m]: contiguous in m. 16 k-rows x 16 float4.
            int kk = tid >> 4;
            int c4 = tid & 15;
            float4 v = *(const float4*)&Ab[(long)(k0 + kk) * lda + m0 + c4 * 4];
            *(float4*)&As[kk][c4 * 4] = v;
        } else {
            // A row-major [m][k]: 64 rows x 4 float4 per row. Transpose on store.
            int r  = tid >> 2;
            int c4 = tid & 3;
            float4 v = *(const float4*)&Ab[(long)(m0 + r) * lda + k0 + c4 * 4];
            As[c4 * 4 + 0][r] = v.x;
            As[c4 * 4 + 1][r] = v.y;
            As[c4 * 4 + 2][r] = v.z;
            As[c4 * 4 + 3][r] = v.w;
        }
        // --- load B tile into Bs[k][n] ---
        {
            int kk = tid >> 4;
            int c4 = tid & 15;
            float4 v = *(const float4*)&Bb[(long)(k0 + kk) * ldb + n0 + c4 * 4];
            *(float4*)&Bs[kk][c4 * 4] = v;
        }
        __syncthreads();

        #pragma unroll
        for (int k = 0; k < 16; k++) {
            float4 a4 = *(const float4*)&As[k][ty * 4];
            float4 b4 = *(const float4*)&Bs[k][tx * 4];
            float a[4] = {a4.x, a4.y, a4.z, a4.w};
            float bb[4] = {b4.x, b4.y, b4.z, b4.w};
            #pragma unroll
            for (int i = 0; i < 4; i++)
                #pragma unroll
                for (int jj = 0; jj < 4; jj++)
                    acc[i][jj] = fmaf(a[i], bb[jj], acc[i][jj]);
        }
        __syncthreads();
    }

    // --- epilogue ---
    float4 bv = make_float4(0.f, 0.f, 0.f, 0.f);
    if (MODE != 2) bv = *(const float4*)&bias[n0 + tx * 4];

    #pragma unroll
    for (int mm = 0; mm < 4; mm++) {
        int r = m0 + ty * 4 + mm;
        float4 v = make_float4(acc[mm][0], acc[mm][1], acc[mm][2], acc[mm][3]);
        if (MODE == 0) {
            float s = srow[r];
            v.x = fmaxf(fmaf(s, bv.x, v.x), 0.f);
            v.y = fmaxf(fmaf(s, bv.y, v.y), 0.f);
            v.z = fmaxf(fmaf(s, bv.z, v.z), 0.f);
            v.w = fmaxf(fmaf(s, bv.w, v.w), 0.f);
        } else if (MODE == 1) {
            float wv = wmul[r];
            v.x = (v.x + bv.x) * wv;
            v.y = (v.y + bv.y) * wv;
            v.z = (v.z + bv.z) * wv;
            v.w = (v.w + bv.w) * wv;
        }
        *(float4*)&Cb[(long)r * ldc + n0 + tx * 4] = v;
    }
}

// ---------------------------------------------------------------------------
extern "C" void kernel_launch(void* const* d_in, const int* in_sizes, int n_in,
                              void* d_out, int out_size) {
    const float* X    = (const float*)d_in[0];   // [16,128,256]
    const float* E    = (const float*)d_in[1];   // [16,128,128,128]
    const float* A    = (const float*)d_in[2];   // [16,128,128]
    const float* w    = (const float*)d_in[3];   // [16,128,1]
    const float* Wv_w = (const float*)d_in[4];   // [256,256]
    const float* Wv_b = (const float*)d_in[5];   // [256]
    const float* We_w = (const float*)d_in[6];   // [128,128]
    const float* We_b = (const float*)d_in[7];   // [128]
    const float* Wu_w = (const float*)d_in[8];   // [640,256]
    const float* Wu_b = (const float*)d_in[9];   // [256]
    float* out = (float*)d_out;                  // [16,128,256]

    float *aggE, *sA, *AX, *H;
    cudaGetSymbolAddress((void**)&aggE, d_aggE);
    cudaGetSymbolAddress((void**)&sA,   d_sA);
    cudaGetSymbolAddress((void**)&AX,   d_AX);
    cudaGetSymbolAddress((void**)&H,    d_H);

    // 1. E-reduction (HBM-bound, 134 MB)
    ereduce_kernel<<<dim3(MM / 4, BB), 128>>>(E, A);

    // 2. relu(X) -> H[:, 384:640]
    relux_kernel<<<(ROWS * NHD / 4) / 256, 256>>>(X);

    // 3. AX[b] = A[b]^T @ X[b]   (batched over z, raw store)
    gemm_kernel<true, 2><<<dim3(MM / 64, NHD / 64, BB), 256>>>(
        A, MM, (long)MM * MM,
        X, NHD, (long)MM * NHD,
        AX, NHD, (long)MM * NHD,
        MM, nullptr, nullptr, nullptr);

    // 4. H[:,0:256] = relu(AX @ Wv_w + sA*Wv_b)
    gemm_kernel<false, 0><<<dim3(ROWS / 64, NHD / 64, 1), 256>>>(
        AX, NHD, 0,
        Wv_w, NHD, 0,
        H, HD, 0,
        NHD, Wv_b, sA, nullptr);

    // 5. H[:,256:384] = relu(aggE @ We_w + sA*We_b)
    gemm_kernel<false, 0><<<dim3(ROWS / 64, EHD / 64, 1), 256>>>(
        aggE, EHD, 0,
        We_w, EHD, 0,
        H + NHD, HD, 0,
        EHD, We_b, sA, nullptr);

    // 6. out = (H @ Wu_w + Wu_b) * w
    gemm_kernel<false, 1><<<dim3(ROWS / 64, NHD / 64, 1), 256>>>(
        H, HD, 0,
        Wu_w, NHD, 0,
        out, NHD, 0,
        HD, Wu_b, nullptr, w);
}

// round 3
// speedup vs baseline: 1.3606x; 1.3606x over previous
#include <cuda_runtime.h>

// Problem dims
#define BB 16
#define MM 128
#define NHD 256
#define EHD 128
#define ROWS (BB*MM)     // 2048
#define NSLAB 5          // final GEMM split-K slabs of 128

// Scratch (static __device__, no allocations)
__device__ __align__(16) float d_aggE[ROWS*EHD];          // Σ_i A*E  [2048][128]
__device__ __align__(16) float d_sA[ROWS];                // colsum of A
__device__ __align__(16) float d_AX[ROWS*NHD];            // A^T @ X  [2048][256]
__device__ __align__(16) float d_Hn[ROWS*NHD];            // relu(node part) [2048][256]
__device__ __align__(16) float d_He[ROWS*EHD];            // relu(edge part) [2048][128]
__device__ __align__(16) float d_part[NSLAB*ROWS*NHD];    // split-K partials (10MB)

// ---------------------------------------------------------------------------
// Kernel 1: aggE[b,j,:] = sum_i A[b,i,j] * E[b,i,j,:]  ;  sA[b,j] = sum_i A[b,i,j]
// grid (M/4, B), block 128.  Each warp owns one j; lane -> float4 over e.
// ---------------------------------------------------------------------------
__global__ void ereduce_kernel(const float* __restrict__ E,
                               const float* __restrict__ A) {
    __shared__ float As[4][MM];
    const int b   = blockIdx.y;
    const int j0  = blockIdx.x * 4;
    const int tid = threadIdx.x;
    const int jl  = tid >> 5;
    const int lane = tid & 31;

    const float* Ab = A + (long)b * MM * MM;
    for (int idx = tid; idx < 4 * MM; idx += 128) {
        int jj = idx & 3;
        int i  = idx >> 2;
        As[jj][i] = Ab[i * MM + j0 + jj];
    }
    __syncthreads();

    if (tid < 4) {
        float s = 0.f;
        #pragma unroll
        for (int i = 0; i < MM; i++) s += As[tid][i];
        d_sA[b * MM + j0 + tid] = s;
    }

    const int j = j0 + jl;
    const float4* Ep = (const float4*)E + ((long)(b * MM) * MM + j) * (EHD / 4) + lane;
    const long istride = (long)MM * (EHD / 4);

    float4 acc = make_float4(0.f, 0.f, 0.f, 0.f);
    #pragma unroll 8
    for (int i = 0; i < MM; i++) {
        float a  = As[jl][i];
        float4 v = Ep[(long)i * istride];
        acc.x = fmaf(a, v.x, acc.x);
        acc.y = fmaf(a, v.y, acc.y);
        acc.z = fmaf(a, v.z, acc.z);
        acc.w = fmaf(a, v.w, acc.w);
    }
    ((float4*)d_aggE)[(b * MM + j) * (EHD / 4) + lane] = acc;
}

// ---------------------------------------------------------------------------
// Generic fp32 tiled GEMM with register-prefetch double buffering.
// Tiles: BM=BN=64, BK=16, 256 threads, 4x4 micro-tile.
// MODE 0: C = relu(acc + srow[r]*bias[n])     (node/edge H segments)
// MODE 2: C = acc                             (AX batched)
// ---------------------------------------------------------------------------
template<bool TRANSA, int MODE>
__global__ __launch_bounds__(256, 4)
void gemm_kernel(const float* __restrict__ Ag, int lda, long strideA,
                 const float* __restrict__ Bg, int ldb, long strideB,
                 float* __restrict__ Cg, int ldc, long strideC,
                 int K,
                 const float* __restrict__ bias,
                 const float* __restrict__ srow) {
    __shared__ float As[16][68];
    __shared__ float Bs[16][68];

    const float* Ab = Ag + (long)blockIdx.z * strideA;
    const float* Bb = Bg + (long)blockIdx.z * strideB;
    float*       Cb = Cg + (long)blockIdx.z * strideC;

    const int m0 = blockIdx.x * 64;
    const int n0 = blockIdx.y * 64;
    const int tid = threadIdx.x;
    const int tx = tid & 15;
    const int ty = tid >> 4;

    float acc[4][4] = {};

    // prologue loads
    float4 ra, rb;
    {
        if (TRANSA) {
            int kk = tid >> 4, c4 = tid & 15;
            ra = *(const float4*)&Ab[(long)kk * lda + m0 + c4 * 4];
        } else {
            int r = tid >> 2, c4 = tid & 3;
            ra = *(const float4*)&Ab[(long)(m0 + r) * lda + c4 * 4];
        }
        int kk = tid >> 4, c4 = tid & 15;
        rb = *(const float4*)&Bb[(long)kk * ldb + n0 + c4 * 4];
    }

    for (int k0 = 0; k0 < K; k0 += 16) {
        // store prefetched tile to smem
        if (TRANSA) {
            int kk = tid >> 4, c4 = tid & 15;
            *(float4*)&As[kk][c4 * 4] = ra;
        } else {
            int r = tid >> 2, c4 = tid & 3;
            As[c4 * 4 + 0][r] = ra.x;
            As[c4 * 4 + 1][r] = ra.y;
            As[c4 * 4 + 2][r] = ra.z;
            As[c4 * 4 + 3][r] = ra.w;
        }
        {
            int kk = tid >> 4, c4 = tid & 15;
            *(float4*)&Bs[kk][c4 * 4] = rb;
        }
        __syncthreads();

        // prefetch next slab while computing this one
        int kn = k0 + 16;
        if (kn < K) {
            if (TRANSA) {
                int kk = tid >> 4, c4 = tid & 15;
                ra = *(const float4*)&Ab[(long)(kn + kk) * lda + m0 + c4 * 4];
            } else {
                int r = tid >> 2, c4 = tid & 3;
                ra = *(const float4*)&Ab[(long)(m0 + r) * lda + kn + c4 * 4];
            }
            int kk = tid >> 4, c4 = tid & 15;
            rb = *(const float4*)&Bb[(long)(kn + kk) * ldb + n0 + c4 * 4];
        }

        #pragma unroll
        for (int k = 0; k < 16; k++) {
            float4 a4 = *(const float4*)&As[k][ty * 4];
            float4 b4 = *(const float4*)&Bs[k][tx * 4];
            float a[4] = {a4.x, a4.y, a4.z, a4.w};
            float bb[4] = {b4.x, b4.y, b4.z, b4.w};
            #pragma unroll
            for (int i = 0; i < 4; i++)
                #pragma unroll
                for (int jj = 0; jj < 4; jj++)
                    acc[i][jj] = fmaf(a[i], bb[jj], acc[i][jj]);
        }
        __syncthreads();
    }

    float4 bv = make_float4(0.f, 0.f, 0.f, 0.f);
    if (MODE == 0) bv = *(const float4*)&bias[n0 + tx * 4];

    #pragma unroll
    for (int mm = 0; mm < 4; mm++) {
        int r = m0 + ty * 4 + mm;
        float4 v = make_float4(acc[mm][0], acc[mm][1], acc[mm][2], acc[mm][3]);
        if (MODE == 0) {
            float s = srow[r];
            v.x = fmaxf(fmaf(s, bv.x, v.x), 0.f);
            v.y = fmaxf(fmaf(s, bv.y, v.y), 0.f);
            v.z = fmaxf(fmaf(s, bv.z, v.z), 0.f);
            v.w = fmaxf(fmaf(s, bv.w, v.w), 0.f);
        }
        *(float4*)&Cb[(long)r * ldc + n0 + tx * 4] = v;
    }
}

// ---------------------------------------------------------------------------
// Final GEMM, split-K over 5 slabs of 128. blockIdx.z = slab.
// A-operand slab sources: {Hn[:,0:128], Hn[:,128:256], He, relu(X[:,0:128]),
// relu(X[:,128:256])}; B = Wu_w[z*128 : z*128+128, :].
// Stores raw partials to d_part[z].
// ---------------------------------------------------------------------------
__global__ __launch_bounds__(256, 4)
void final_partial_kernel(const float* __restrict__ Hn,
                          const float* __restrict__ He,
                          const float* __restrict__ X,
                          const float* __restrict__ Wu_w) {
    __shared__ float As[16][68];
    __shared__ float Bs[16][68];

    const int z = blockIdx.z;
    const float* src; int ld; bool doRelu;
    if      (z == 0) { src = Hn;       ld = NHD; doRelu = false; }
    else if (z == 1) { src = Hn + 128; ld = NHD; doRelu = false; }
    else if (z == 2) { src = He;       ld = EHD; doRelu = false; }
    else if (z == 3) { src = X;        ld = NHD; doRelu = true;  }
    else             { src = X + 128;  ld = NHD; doRelu = true;  }
    const float* Bb = Wu_w + (long)z * 128 * NHD;

    const int m0 = blockIdx.x * 64;
    const int n0 = blockIdx.y * 64;
    const int tid = threadIdx.x;
    const int tx = tid & 15;
    const int ty = tid >> 4;

    float acc[4][4] = {};

    float4 ra, rb;
    {
        int r = tid >> 2, c4 = tid & 3;
        ra = *(const float4*)&src[(long)(m0 + r) * ld + c4 * 4];
        int kk = tid >> 4, c4b = tid & 15;
        rb = *(const float4*)&Bb[(long)kk * NHD + n0 + c4b * 4];
    }

    for (int k0 = 0; k0 < 128; k0 += 16) {
        if (doRelu) {
            ra.x = fmaxf(ra.x, 0.f); ra.y = fmaxf(ra.y, 0.f);
            ra.z = fmaxf(ra.z, 0.f); ra.w = fmaxf(ra.w, 0.f);
        }
        {
            int r = tid >> 2, c4 = tid & 3;
            As[c4 * 4 + 0][r] = ra.x;
            As[c4 * 4 + 1][r] = ra.y;
            As[c4 * 4 + 2][r] = ra.z;
            As[c4 * 4 + 3][r] = ra.w;
            int kk = tid >> 4, c4b = tid & 15;
            *(float4*)&Bs[kk][c4b * 4] = rb;
        }
        __syncthreads();

        int kn = k0 + 16;
        if (kn < 128) {
            int r = tid >> 2, c4 = tid & 3;
            ra = *(const float4*)&src[(long)(m0 + r) * ld + kn + c4 * 4];
            int kk = tid >> 4, c4b = tid & 15;
            rb = *(const float4*)&Bb[(long)(kn + kk) * NHD + n0 + c4b * 4];
        }

        #pragma unroll
        for (int k = 0; k < 16; k++) {
            float4 a4 = *(const float4*)&As[k][ty * 4];
            float4 b4 = *(const float4*)&Bs[k][tx * 4];
            float a[4] = {a4.x, a4.y, a4.z, a4.w};
            float bb[4] = {b4.x, b4.y, b4.z, b4.w};
            #pragma unroll
            for (int i = 0; i < 4; i++)
                #pragma unroll
                for (int jj = 0; jj < 4; jj++)
                    acc[i][jj] = fmaf(a[i], bb[jj], acc[i][jj]);
        }
        __syncthreads();
    }

    float* Cb = d_part + (long)z * ROWS * NHD;
    #pragma unroll
    for (int mm = 0; mm < 4; mm++) {
        int r = m0 + ty * 4 + mm;
        float4 v = make_float4(acc[mm][0], acc[mm][1], acc[mm][2], acc[mm][3]);
        *(float4*)&Cb[(long)r * NHD + n0 + tx * 4] = v;
    }
}

// ---------------------------------------------------------------------------
// Reduce partials: out[r,n] = (sum_s part[s][r][n] + Wu_b[n]) * w[r]
// ---------------------------------------------------------------------------
__global__ void reduce_kernel(const float* __restrict__ bias,
                              const float* __restrict__ w,
                              float* __restrict__ out) {
    int idx = blockIdx.x * blockDim.x + threadIdx.x;  // float4 idx, 131072 total
    int r  = idx >> 6;
    int c4 = idx & 63;
    const float4* p = (const float4*)d_part;
    const int S = ROWS * NHD / 4;
    float4 a = p[idx];
    #pragma unroll
    for (int s = 1; s < NSLAB; s++) {
        float4 t = p[idx + s * S];
        a.x += t.x; a.y += t.y; a.z += t.z; a.w += t.w;
    }
    float4 b4 = *(const float4*)&bias[c4 * 4];
    float wv = w[r];
    a.x = (a.x + b4.x) * wv;
    a.y = (a.y + b4.y) * wv;
    a.z = (a.z + b4.z) * wv;
    a.w = (a.w + b4.w) * wv;
    ((float4*)out)[idx] = a;
}

// ---------------------------------------------------------------------------
extern "C" void kernel_launch(void* const* d_in, const int* in_sizes, int n_in,
                              void* d_out, int out_size) {
    const float* X    = (const float*)d_in[0];   // [16,128,256]
    const float* E    = (const float*)d_in[1];   // [16,128,128,128]
    const float* A    = (const float*)d_in[2];   // [16,128,128]
    const float* w    = (const float*)d_in[3];   // [16,128,1]
    const float* Wv_w = (const float*)d_in[4];   // [256,256]
    const float* Wv_b = (const float*)d_in[5];   // [256]
    const float* We_w = (const float*)d_in[6];   // [128,128]
    const float* We_b = (const float*)d_in[7];   // [128]
    const float* Wu_w = (const float*)d_in[8];   // [640,256]
    const float* Wu_b = (const float*)d_in[9];   // [256]
    float* out = (float*)d_out;                  // [16,128,256]

    float *aggE, *sA, *AX, *Hn, *He;
    cudaGetSymbolAddress((void**)&aggE, d_aggE);
    cudaGetSymbolAddress((void**)&sA,   d_sA);
    cudaGetSymbolAddress((void**)&AX,   d_AX);
    cudaGetSymbolAddress((void**)&Hn,   d_Hn);
    cudaGetSymbolAddress((void**)&He,   d_He);

    // 1. E-reduction (HBM-bound, 134 MB)
    ereduce_kernel<<<dim3(MM / 4, BB), 128>>>(E, A);

    // 2. AX[b] = A[b]^T @ X[b]   (batched, raw store)
    gemm_kernel<true, 2><<<dim3(MM / 64, NHD / 64, BB), 256>>>(
        A, MM, (long)MM * MM,
        X, NHD, (long)MM * NHD,
        AX, NHD, (long)MM * NHD,
        MM, nullptr, nullptr);

    // 3. Hn = relu(AX @ Wv_w + sA*Wv_b)
    gemm_kernel<false, 0><<<dim3(ROWS / 64, NHD / 64, 1), 256>>>(
        AX, NHD, 0,
        Wv_w, NHD, 0,
        Hn, NHD, 0,
        NHD, Wv_b, sA);

    // 4. He = relu(aggE @ We_w + sA*We_b)
    gemm_kernel<false, 0><<<dim3(ROWS / 64, EHD / 64, 1), 256>>>(
        aggE, EHD, 0,
        We_w, EHD, 0,
        He, EHD, 0,
        EHD, We_b, sA);

    // 5. Split-K final GEMM partials (reads Hn/He/relu(X) directly)
    final_partial_kernel<<<dim3(ROWS / 64, NHD / 64, NSLAB), 256>>>(
        Hn, He, X, Wu_w);

    // 6. Reduce + bias + w scale
    reduce_kernel<<<(ROWS * NHD / 4) / 256, 256>>>(Wu_b, w, out);
}

// round 5
// speedup vs baseline: 1.9466x; 1.4307x over previous
#include <cuda_runtime.h>

// Problem dims
#define BB 16
#define MM 128
#define NHD 256
#define EHD 128
#define ROWS (BB*MM)     // 2048
#define NSLAB 5          // final GEMM split-K slabs of 128

// Scratch (static __device__, no allocations)
__device__ __align__(16) float d_aggE[ROWS*EHD];          // Σ_i A*E  [2048][128]
__device__ __align__(16) float d_sA[ROWS];                // colsum of A
__device__ __align__(16) float d_AX[ROWS*NHD];            // A^T @ X  [2048][256]
__device__ __align__(16) float d_Hn[ROWS*NHD];            // relu(node) [2048][256]
__device__ __align__(16) float d_He[ROWS*EHD];            // relu(edge) [2048][128]
__device__ __align__(16) float d_part[NSLAB*ROWS*NHD];    // split-K partials

#define SMEM_FLOATS (2*16*68)   // 2176 floats = 8704 B (GEMM tiles; ereduce reuses)

// ---------------------------------------------------------------------------
// Device GEMM: 64x64 tile, BK=16, 256 threads, 4x4 micro-tile,
// register-prefetch double buffering.
//   TRANSA: A is [k][m] (read transposed);  else A row-major [m][k]
//   RELUA : apply relu to A elements on load (for raw X slabs)
//   EPI   : epilogue relu(acc + srow[r]*bias[n]); else raw store
// ---------------------------------------------------------------------------
template<bool TRANSA, bool RELUA, bool EPI>
__device__ __forceinline__
void devgemm(const float* __restrict__ Ab, int lda,
             const float* __restrict__ Bb, int ldb,
             float* __restrict__ Cb, int ldc, int K,
             const float* __restrict__ bias,
             const float* __restrict__ srow,
             int m0, int n0, float* sm) {
    float (*As)[68] = (float(*)[68])sm;
    float (*Bs)[68] = (float(*)[68])(sm + 16*68);

    const int tid = threadIdx.x;
    const int tx = tid & 15;
    const int ty = tid >> 4;

    float acc[4][4] = {};

    float4 ra, rb;
    {
        if (TRANSA) {
            int kk = tid >> 4, c4 = tid & 15;
            ra = *(const float4*)&Ab[(long)kk * lda + m0 + c4 * 4];
        } else {
            int r = tid >> 2, c4 = tid & 3;
            ra = *(const float4*)&Ab[(long)(m0 + r) * lda + c4 * 4];
        }
        int kk = tid >> 4, c4 = tid & 15;
        rb = *(const float4*)&Bb[(long)kk * ldb + n0 + c4 * 4];
    }

    for (int k0 = 0; k0 < K; k0 += 16) {
        if (RELUA) {
            ra.x = fmaxf(ra.x, 0.f); ra.y = fmaxf(ra.y, 0.f);
            ra.z = fmaxf(ra.z, 0.f); ra.w = fmaxf(ra.w, 0.f);
        }
        if (TRANSA) {
            int kk = tid >> 4, c4 = tid & 15;
            *(float4*)&As[kk][c4 * 4] = ra;
        } else {
            int r = tid >> 2, c4 = tid & 3;
            As[c4 * 4 + 0][r] = ra.x;
            As[c4 * 4 + 1][r] = ra.y;
            As[c4 * 4 + 2][r] = ra.z;
            As[c4 * 4 + 3][r] = ra.w;
        }
        {
            int kk = tid >> 4, c4 = tid & 15;
            *(float4*)&Bs[kk][c4 * 4] = rb;
        }
        __syncthreads();

        int kn = k0 + 16;
        if (kn < K) {
            if (TRANSA) {
                int kk = tid >> 4, c4 = tid & 15;
                ra = *(const float4*)&Ab[(long)(kn + kk) * lda + m0 + c4 * 4];
            } else {
                int r = tid >> 2, c4 = tid & 3;
                ra = *(const float4*)&Ab[(long)(m0 + r) * lda + kn + c4 * 4];
            }
            int kk = tid >> 4, c4 = tid & 15;
            rb = *(const float4*)&Bb[(long)(kn + kk) * ldb + n0 + c4 * 4];
        }

        #pragma unroll
        for (int k = 0; k < 16; k++) {
            float4 a4 = *(const float4*)&As[k][ty * 4];
            float4 b4 = *(const float4*)&Bs[k][tx * 4];
            float a[4] = {a4.x, a4.y, a4.z, a4.w};
            float bb[4] = {b4.x, b4.y, b4.z, b4.w};
            #pragma unroll
            for (int i = 0; i < 4; i++)
                #pragma unroll
                for (int jj = 0; jj < 4; jj++)
                    acc[i][jj] = fmaf(a[i], bb[jj], acc[i][jj]);
        }
        __syncthreads();
    }

    float4 bv = make_float4(0.f, 0.f, 0.f, 0.f);
    if (EPI) bv = *(const float4*)&bias[n0 + tx * 4];

    #pragma unroll
    for (int mm = 0; mm < 4; mm++) {
        int r = m0 + ty * 4 + mm;
        float4 v = make_float4(acc[mm][0], acc[mm][1], acc[mm][2], acc[mm][3]);
        if (EPI) {
            float s = srow[r];
            v.x = fmaxf(fmaf(s, bv.x, v.x), 0.f);
            v.y = fmaxf(fmaf(s, bv.y, v.y), 0.f);
            v.z = fmaxf(fmaf(s, bv.z, v.z), 0.f);
            v.w = fmaxf(fmaf(s, bv.w, v.w), 0.f);
        }
        *(float4*)&Cb[(long)r * ldc + n0 + tx * 4] = v;
    }
}

// ---------------------------------------------------------------------------
// Device ereduce: 256 threads, 8 j's per block (one per warp).
// aggE[b,j,:] = sum_i A[b,i,j]*E[b,i,j,:] ;  sA[b,j] = sum_i A[b,i,j]
// ---------------------------------------------------------------------------
__device__ __forceinline__
void ereduce8(const float* __restrict__ E, const float* __restrict__ A,
              int b, int jg, float* sm) {
    float (*As)[MM] = (float(*)[MM])sm;   // [8][128]
    const int tid = threadIdx.x;
    const int jl  = tid >> 5;
    const int lane = tid & 31;
    const int j0 = jg * 8;

    const float* Ab = A + (long)b * MM * MM;
    for (int idx = tid; idx < 8 * MM; idx += 256) {
        int jj = idx & 7;
        int i  = idx >> 3;
        As[jj][i] = Ab[i * MM + j0 + jj];
    }
    __syncthreads();

    if (tid < 8) {
        float s = 0.f;
        #pragma unroll
        for (int i = 0; i < MM; i++) s += As[tid][i];
        d_sA[b * MM + j0 + tid] = s;
    }

    const int j = j0 + jl;
    const float4* Ep = (const float4*)E + ((long)(b * MM) * MM + j) * (EHD / 4) + lane;
    const long istride = (long)MM * (EHD / 4);

    float4 acc = make_float4(0.f, 0.f, 0.f, 0.f);
    #pragma unroll 8
    for (int i = 0; i < MM; i++) {
        float a  = As[jl][i];
        float4 v = Ep[(long)i * istride];
        acc.x = fmaf(a, v.x, acc.x);
        acc.y = fmaf(a, v.y, acc.y);
        acc.z = fmaf(a, v.z, acc.z);
        acc.w = fmaf(a, v.w, acc.w);
    }
    ((float4*)d_aggE)[(b * MM + j) * (EHD / 4) + lane] = acc;
}

// ---------------------------------------------------------------------------
// Phase 1 (640 blocks): ereduce [0,256) | AX [256,384) | final slabs 3,4 [384,640)
// ---------------------------------------------------------------------------
__global__ __launch_bounds__(256, 4)
void phase1_kernel(const float* __restrict__ E, const float* __restrict__ A,
                   const float* __restrict__ X, const float* __restrict__ Wu_w) {
    __shared__ float sm[SMEM_FLOATS];
    const int blk = blockIdx.x;

    if (blk < 256) {
        ereduce8(E, A, blk >> 4, blk & 15, sm);
    } else if (blk < 384) {
        // AX[b] = A[b]^T @ X[b] : per batch 2 m-tiles x 4 n-tiles
        int idx = blk - 256;
        int b = idx >> 3, t = idx & 7;
        int mt = t >> 2, nt = t & 3;
        devgemm<true, false, false>(
            A + (long)b * MM * MM, MM,
            X + (long)b * MM * NHD, NHD,
            d_AX + (long)b * MM * NHD, NHD,
            MM, nullptr, nullptr, mt * 64, nt * 64, sm);
    } else {
        // final slabs 3,4: relu(X[:, s*128 : s*128+128]) @ Wu_w[384+s*128 ...]
        int idx = blk - 384;
        int s = idx >> 7;            // 0 or 1
        int r = idx & 127;
        int mt = r >> 2, nt = r & 3;
        devgemm<false, true, false>(
            X + s * 128, NHD,
            Wu_w + (long)(384 + s * 128) * NHD, NHD,
            d_part + (long)(3 + s) * ROWS * NHD, NHD,
            128, nullptr, nullptr, mt * 64, nt * 64, sm);
    }
}

// ---------------------------------------------------------------------------
// Phase 2 (192 blocks): Hn [0,128) | He [128,192)
// ---------------------------------------------------------------------------
__global__ __launch_bounds__(256, 4)
void phase2_kernel(const float* __restrict__ Wv_w, const float* __restrict__ Wv_b,
                   const float* __restrict__ We_w, const float* __restrict__ We_b) {
    __shared__ float sm[SMEM_FLOATS];
    const int blk = blockIdx.x;
    if (blk < 128) {
        int mt = blk >> 2, nt = blk & 3;   // 32 x 4
        devgemm<false, false, true>(
            d_AX, NHD, Wv_w, NHD, d_Hn, NHD,
            NHD, Wv_b, d_sA, mt * 64, nt * 64, sm);
    } else {
        int idx = blk - 128;
        int mt = idx >> 1, nt = idx & 1;   // 32 x 2
        devgemm<false, false, true>(
            d_aggE, EHD, We_w, EHD, d_He, EHD,
            EHD, We_b, d_sA, mt * 64, nt * 64, sm);
    }
}

// ---------------------------------------------------------------------------
// Phase 3 (384 blocks): final slabs 0,1 (Hn), 2 (He)
// ---------------------------------------------------------------------------
__global__ __launch_bounds__(256, 4)
void phase3_kernel(const float* __restrict__ Wu_w) {
    __shared__ float sm[SMEM_FLOATS];
    const int blk = blockIdx.x;
    const int s = blk >> 7;       // 0,1,2
    const int r = blk & 127;
    const int mt = r >> 2, nt = r & 3;
    const float* src;
    int ld;
    if (s == 0)      { src = d_Hn;       ld = NHD; }
    else if (s == 1) { src = d_Hn + 128; ld = NHD; }
    else             { src = d_He;       ld = EHD; }
    devgemm<false, false, false>(
        src, ld,
        Wu_w + (long)(s * 128) * NHD, NHD,
        d_part + (long)s * ROWS * NHD, NHD,
        128, nullptr, nullptr, mt * 64, nt * 64, sm);
}

// ---------------------------------------------------------------------------
// Reduce partials: out[r,n] = (sum_s part[s][r][n] + Wu_b[n]) * w[r]
// ---------------------------------------------------------------------------
__global__ void reduce_kernel(const float* __restrict__ bias,
                              const float* __restrict__ w,
                              float* __restrict__ out) {
    int idx = blockIdx.x * blockDim.x + threadIdx.x;
    int r  = idx >> 6;
    int c4 = idx & 63;
    const float4* p = (const float4*)d_part;
    const int S = ROWS * NHD / 4;
    float4 a = p[idx];
    #pragma unroll
    for (int s = 1; s < NSLAB; s++) {
        float4 t = p[idx + s * S];
        a.x += t.x; a.y += t.y; a.z += t.z; a.w += t.w;
    }
    float4 b4 = *(const float4*)&bias[c4 * 4];
    float wv = w[r];
    a.x = (a.x + b4.x) * wv;
    a.y = (a.y + b4.y) * wv;
    a.z = (a.z + b4.z) * wv;
    a.w = (a.w + b4.w) * wv;
    ((float4*)out)[idx] = a;
}

// ---------------------------------------------------------------------------
extern "C" void kernel_launch(void* const* d_in, const int* in_sizes, int n_in,
                              void* d_out, int out_size) {
    const float* X    = (const float*)d_in[0];   // [16,128,256]
    const float* E    = (const float*)d_in[1];   // [16,128,128,128]
    const float* A    = (const float*)d_in[2];   // [16,128,128]
    const float* w    = (const float*)d_in[3];   // [16,128,1]
    const float* Wv_w = (const float*)d_in[4];   // [256,256]
    const float* Wv_b = (const float*)d_in[5];   // [256]
    const float* We_w = (const float*)d_in[6];   // [128,128]
    const float* We_b = (const float*)d_in[7];   // [128]
    const float* Wu_w = (const float*)d_in[8];   // [640,256]
    const float* Wu_b = (const float*)d_in[9];   // [256]
    float* out = (float*)d_out;                  // [16,128,256]

    // Phase 1: ereduce + AX + final slabs 3,4 (independent, fills machine)
    phase1_kernel<<<640, 256>>>(E, A, X, Wu_w);

    // Phase 2: Hn and He GEMMs
    phase2_kernel<<<192, 256>>>(Wv_w, Wv_b, We_w, We_b);

    // Phase 3: final slabs 0,1,2
    phase3_kernel<<<384, 256>>>(Wu_w);

    // Phase 4: reduce + bias + w scale
    reduce_kernel<<<(ROWS * NHD / 4) / 256, 256>>>(Wu_b, w, out);
}